// round 3
// baseline (speedup 1.0000x reference)
#include <cuda_runtime.h>

// ---------------------------------------------------------------------------
// Problem constants
// ---------------------------------------------------------------------------
#define BATCH    16384
#define MROWS    (BATCH * 3)     // 49152 rows for the projection GEMMs
#define EMB      256             // projected embedding dim
#define ROW      768             // 3 * EMB, flattened row length
#define EPS      1e-8f

// GEMM tiling
#define BM  128
#define BN  128
#define BKK 16

// ---------------------------------------------------------------------------
// Scratch (device globals; no allocation allowed)
// ---------------------------------------------------------------------------
__device__ float g_H [(size_t)MROWS * 768];   // hidden activations (reused)
__device__ float g_ht[(size_t)MROWS * EMB];
__device__ float g_tt[(size_t)MROWS * EMB];
__device__ float g_hs[(size_t)MROWS * EMB];
__device__ float g_ts[(size_t)MROWS * EMB];
__device__ float g_dts[2][MROWS];   // per (pair, row*3+slot): dot(t_slot, s_slot)
__device__ float g_qa [2][MROWS];   // |t_slot|^2
__device__ float g_qb [2][MROWS];   // |s_slot|^2
__device__ float g_P  [2 * BATCH];  // pos_sim per (branch, b)
__device__ float g_Ng [2 * BATCH];  // neg_sim per (branch, b)
__device__ float g_partial[64];

// ---------------------------------------------------------------------------
// Helpers
// ---------------------------------------------------------------------------
__device__ __forceinline__ float dot4(float4 a, float4 b) {
    return a.x * b.x + a.y * b.y + a.z * b.z + a.w * b.w;
}

__device__ __forceinline__ float wred(float v) {
#pragma unroll
    for (int o = 16; o; o >>= 1) v += __shfl_xor_sync(0xFFFFFFFFu, v, o);
    return v;
}

__device__ __forceinline__ float cosv(float d, float na2, float nb2) {
    float na = fmaxf(sqrtf(na2), EPS);
    float nb = fmaxf(sqrtf(nb2), EPS);
    return d / (na * nb);
}

// ---------------------------------------------------------------------------
// GEMM: C[M,N] = act(A[M,K] @ W[K,N] + bias[N]); M%128==0, N%128==0, K%16==0
// 256 threads, 128x128 tile, 8x8 per thread, double-buffered smem.
// ---------------------------------------------------------------------------
template <bool RELU>
__global__ void __launch_bounds__(256, 2)
gemm_bias_kernel(const float* __restrict__ A, const float* __restrict__ W,
                 const float* __restrict__ bias, float* __restrict__ C,
                 int M, int N, int K) {
    __shared__ float As[2][BKK][BM];
    __shared__ float Bs[2][BKK][BN];

    const int tid = threadIdx.x;
    const int n0 = blockIdx.x * BN;
    const int m0 = blockIdx.y * BM;
    const float* Ab = A + (size_t)m0 * K;
    const float* Wb = W + n0;

    float acc[8][8];
#pragma unroll
    for (int i = 0; i < 8; i++)
#pragma unroll
        for (int j = 0; j < 8; j++) acc[i][j] = 0.f;

    const int q0 = tid, q1 = tid + 256;
    const int ar0 = q0 >> 2, akc0 = (q0 & 3) << 2;
    const int ar1 = q1 >> 2, akc1 = (q1 & 3) << 2;
    const int bk0 = q0 >> 5, bc0 = (q0 & 31) << 2;
    const int bk1 = q1 >> 5, bc1 = (q1 & 31) << 2;

    float4 a0, a1, b0, b1;

    // prologue fetch + stage
    a0 = *(const float4*)(Ab + (size_t)ar0 * K + akc0);
    a1 = *(const float4*)(Ab + (size_t)ar1 * K + akc1);
    b0 = *(const float4*)(Wb + (size_t)bk0 * N + bc0);
    b1 = *(const float4*)(Wb + (size_t)bk1 * N + bc1);
    As[0][akc0 + 0][ar0] = a0.x; As[0][akc0 + 1][ar0] = a0.y;
    As[0][akc0 + 2][ar0] = a0.z; As[0][akc0 + 3][ar0] = a0.w;
    As[0][akc1 + 0][ar1] = a1.x; As[0][akc1 + 1][ar1] = a1.y;
    As[0][akc1 + 2][ar1] = a1.z; As[0][akc1 + 3][ar1] = a1.w;
    *(float4*)&Bs[0][bk0][bc0] = b0;
    *(float4*)&Bs[0][bk1][bc1] = b1;
    __syncthreads();

    const int ty = tid >> 4, tx = tid & 15;
    const int row0 = ty * 8, col0 = tx * 8;
    const int nk = K / BKK;

    for (int kt = 0; kt < nk; kt++) {
        const int buf = kt & 1;
        if (kt + 1 < nk) {
            const int k0 = (kt + 1) * BKK;
            a0 = *(const float4*)(Ab + (size_t)ar0 * K + k0 + akc0);
            a1 = *(const float4*)(Ab + (size_t)ar1 * K + k0 + akc1);
            b0 = *(const float4*)(Wb + (size_t)(k0 + bk0) * N + bc0);
            b1 = *(const float4*)(Wb + (size_t)(k0 + bk1) * N + bc1);
        }
#pragma unroll
        for (int k = 0; k < BKK; k++) {
            float ar[8], br[8];
            *(float4*)(ar)     = *(const float4*)&As[buf][k][row0];
            *(float4*)(ar + 4) = *(const float4*)&As[buf][k][row0 + 4];
            *(float4*)(br)     = *(const float4*)&Bs[buf][k][col0];
            *(float4*)(br + 4) = *(const float4*)&Bs[buf][k][col0 + 4];
#pragma unroll
            for (int i = 0; i < 8; i++)
#pragma unroll
                for (int j = 0; j < 8; j++)
                    acc[i][j] += ar[i] * br[j];
        }
        if (kt + 1 < nk) {
            const int nb = buf ^ 1;
            As[nb][akc0 + 0][ar0] = a0.x; As[nb][akc0 + 1][ar0] = a0.y;
            As[nb][akc0 + 2][ar0] = a0.z; As[nb][akc0 + 3][ar0] = a0.w;
            As[nb][akc1 + 0][ar1] = a1.x; As[nb][akc1 + 1][ar1] = a1.y;
            As[nb][akc1 + 2][ar1] = a1.z; As[nb][akc1 + 3][ar1] = a1.w;
            *(float4*)&Bs[nb][bk0][bc0] = b0;
            *(float4*)&Bs[nb][bk1][bc1] = b1;
        }
        __syncthreads();
    }

    // epilogue: bias (+relu) and store
    float bv[8];
    {
        float4 t0 = *(const float4*)(bias + n0 + col0);
        float4 t1 = *(const float4*)(bias + n0 + col0 + 4);
        bv[0] = t0.x; bv[1] = t0.y; bv[2] = t0.z; bv[3] = t0.w;
        bv[4] = t1.x; bv[5] = t1.y; bv[6] = t1.z; bv[7] = t1.w;
    }
#pragma unroll
    for (int i = 0; i < 8; i++) {
        float* crow = C + (size_t)(m0 + row0 + i) * N + (n0 + col0);
        float v[8];
#pragma unroll
        for (int j = 0; j < 8; j++) {
            v[j] = acc[i][j] + bv[j];
            if (RELU) v[j] = fmaxf(v[j], 0.f);
        }
        float4 o0, o1;
        o0.x = v[0]; o0.y = v[1]; o0.z = v[2]; o0.w = v[3];
        o1.x = v[4]; o1.y = v[5]; o1.z = v[6]; o1.w = v[7];
        *(float4*)crow       = o0;
        *(float4*)(crow + 4) = o1;
    }
}

// ---------------------------------------------------------------------------
// Per-(row,slot) stats: dot(t_slot, s_slot), |t_slot|^2, |s_slot|^2.
// One warp per (row*3+slot). pair j=0 -> (ht, ts); j=1 -> (tt, hs).
// ---------------------------------------------------------------------------
__global__ void __launch_bounds__(256) stats_kernel(int j) {
    const int wg = (blockIdx.x * blockDim.x + threadIdx.x) >> 5;
    if (wg >= MROWS) return;
    const int lane = threadIdx.x & 31;
    const float* T = j ? g_tt : g_ht;
    const float* S = j ? g_hs : g_ts;
    const float* t = T + (size_t)wg * EMB + lane * 4;
    const float* s = S + (size_t)wg * EMB + lane * 4;
    float d = 0.f, a = 0.f, b = 0.f;
#pragma unroll
    for (int w = 0; w < 2; w++) {
        float4 tv = *(const float4*)(t + w * 128);
        float4 sv = *(const float4*)(s + w * 128);
        d += dot4(tv, sv);
        a += dot4(tv, tv);
        b += dot4(sv, sv);
    }
    d = wred(d); a = wred(a); b = wred(b);
    if (lane == 0) {
        g_dts[j][wg] = d;
        g_qa[j][wg]  = a;
        g_qb[j][wg]  = b;
    }
}

// ---------------------------------------------------------------------------
// Branch kernel: one warp per (branch j, row b). Computes pos_sim, neg_sim.
// ---------------------------------------------------------------------------
__global__ void __launch_bounds__(256) branch_kernel(const int* __restrict__ perms) {
    const int wg = (blockIdx.x * blockDim.x + threadIdx.x) >> 5;
    if (wg >= 2 * BATCH) return;
    const int lane = threadIdx.x & 31;
    const int j = wg >> 14;          // BATCH = 2^14
    const int b = wg & (BATCH - 1);

    const float* T = j ? g_tt : g_ht;
    const float* S = j ? g_hs : g_ts;
    const float* dts = g_dts[j];
    const float* qa3 = g_qa[j];
    const float* qb3 = g_qb[j];
    const int* p = perms + j * 8 * BATCH;

    // Own rows resident in registers
    float4 trv[6], srv[6];
    const float* trow = T + (size_t)b * ROW + lane * 4;
    const float* srow = S + (size_t)b * ROW + lane * 4;
#pragma unroll
    for (int w = 0; w < 6; w++) {
        trv[w] = *(const float4*)(trow + w * 128);
        srv[w] = *(const float4*)(srow + w * 128);
    }
    float dp = 0.f, qa = 0.f, qb = 0.f;
#pragma unroll
    for (int w = 0; w < 6; w++) {
        dp += dot4(trv[w], srv[w]);
        qa += dot4(trv[w], trv[w]);
        qb += dot4(srv[w], srv[w]);
    }
    dp = wred(dp); qa = wred(qa); qb = wred(qb);

    // Full-row shuffle negatives: 4 gathered 768-dim dots
    const int p4 = p[4 * BATCH + b], p5 = p[5 * BATCH + b];
    const int p6 = p[6 * BATCH + b], p7 = p[7 * BATCH + b];
    const float* r4 = T + (size_t)p4 * ROW + lane * 4;
    const float* r5 = S + (size_t)p5 * ROW + lane * 4;
    const float* r6 = T + (size_t)p6 * ROW + lane * 4;
    const float* r7 = S + (size_t)p7 * ROW + lane * 4;
    float d4 = 0.f, d5 = 0.f, d6 = 0.f, d7 = 0.f;
#pragma unroll
    for (int w = 0; w < 6; w++) {
        d4 += dot4(*(const float4*)(r4 + w * 128), srv[w]);
        d6 += dot4(*(const float4*)(r6 + w * 128), srv[w]);
        d5 += dot4(*(const float4*)(r5 + w * 128), trv[w]);
        d7 += dot4(*(const float4*)(r7 + w * 128), trv[w]);
    }
    d4 = wred(d4); d5 = wred(d5); d6 = wred(d6); d7 = wred(d7);

    if (lane == 0) {
        const int p0 = p[b], p1 = p[BATCH + b];
        const int p2 = p[2 * BATCH + b], p3 = p[3 * BATCH + b];
        const int b3 = b * 3;
        const float dt0 = dts[b3], dt1 = dts[b3 + 1], dt2 = dts[b3 + 2];
        const float a0 = qa3[b3], a1 = qa3[b3 + 1], a2 = qa3[b3 + 2];
        const float q0 = qb3[b3], q1 = qb3[b3 + 1], q2 = qb3[b3 + 2];

        float neg = 0.f;
        // tail-slot swap (perm p0)
        neg += expf(cosv(dt0 + dt1 + dts[p0 * 3 + 2],
                         a0 + a1 + qa3[p0 * 3 + 2],
                         q0 + q1 + qb3[p0 * 3 + 2]));
        // head-slot swap (perm p1)
        neg += expf(cosv(dts[p1 * 3] + dt1 + dt2,
                         qa3[p1 * 3] + a1 + a2,
                         qb3[p1 * 3] + q1 + q2));
        // tail-slot swap (perm p2)
        neg += expf(cosv(dt0 + dt1 + dts[p2 * 3 + 2],
                         a0 + a1 + qa3[p2 * 3 + 2],
                         q0 + q1 + qb3[p2 * 3 + 2]));
        // head-slot swap (perm p3)
        neg += expf(cosv(dts[p3 * 3] + dt1 + dt2,
                         qa3[p3 * 3] + a1 + a2,
                         qb3[p3 * 3] + q1 + q2));
        // full shuffles
        neg += expf(cosv(d4, qa3[p4 * 3] + qa3[p4 * 3 + 1] + qa3[p4 * 3 + 2], qb));
        neg += expf(cosv(d5, qa, qb3[p5 * 3] + qb3[p5 * 3 + 1] + qb3[p5 * 3 + 2]));
        neg += expf(cosv(d6, qa3[p6 * 3] + qa3[p6 * 3 + 1] + qa3[p6 * 3 + 2], qb));
        neg += expf(cosv(d7, qa, qb3[p7 * 3] + qb3[p7 * 3 + 1] + qb3[p7 * 3 + 2]));

        g_P[wg]  = expf(cosv(dp, qa, qb));
        g_Ng[wg] = neg;
    }
}

// ---------------------------------------------------------------------------
// score + deterministic two-stage loss reduction
// ---------------------------------------------------------------------------
__global__ void __launch_bounds__(256) score_loss_kernel(const float* __restrict__ conf,
                                                         float* __restrict__ out) {
    __shared__ float sm[256];
    float local = 0.f;
    for (int b = blockIdx.x * 256 + threadIdx.x; b < BATCH; b += 256 * gridDim.x) {
        float p0 = g_P[b],          n0 = g_Ng[b];
        float p1 = g_P[BATCH + b],  n1 = g_Ng[BATCH + b];
        out[1 + b] = -(p0 + p1);
        local += -conf[b] * (logf(p0 / (p0 + n0)) + logf(p1 / (p1 + n1)));
    }
    sm[threadIdx.x] = local;
    __syncthreads();
    for (int s = 128; s; s >>= 1) {
        if (threadIdx.x < s) sm[threadIdx.x] += sm[threadIdx.x + s];
        __syncthreads();
    }
    if (threadIdx.x == 0) g_partial[blockIdx.x] = sm[0];
}

__global__ void loss_final_kernel(float* __restrict__ out, int nPart) {
    __shared__ float sm[64];
    const int t = threadIdx.x;
    sm[t] = (t < nPart) ? g_partial[t] : 0.f;
    __syncthreads();
    for (int s = 32; s; s >>= 1) {
        if (t < s) sm[t] += sm[t + s];
        __syncthreads();
    }
    if (t == 0) out[0] = sm[0] * (1.f / BATCH);
}

// ---------------------------------------------------------------------------
// logits = ht + tt (text), hs + ts (struc). Output base offset 1+BATCH is
// only 4B-aligned, so use scalar (coalesced) stores.
// ---------------------------------------------------------------------------
__global__ void __launch_bounds__(256) logits_kernel(float* __restrict__ out) {
    const size_t n = (size_t)BATCH * ROW;
    float* otext  = out + 1 + BATCH;
    float* ostruc = otext + n;
    for (size_t i = blockIdx.x * (size_t)blockDim.x + threadIdx.x; i < n;
         i += (size_t)gridDim.x * blockDim.x) {
        otext[i]  = g_ht[i] + g_tt[i];
        ostruc[i] = g_hs[i] + g_ts[i];
    }
}

// ---------------------------------------------------------------------------
// Launch
// ---------------------------------------------------------------------------
extern "C" void kernel_launch(void* const* d_in, const int* in_sizes, int n_in,
                              void* d_out, int out_size) {
    const float* head_text  = (const float*)d_in[0];
    const float* tail_text  = (const float*)d_in[1];
    const float* head_struc = (const float*)d_in[2];
    const float* tail_struc = (const float*)d_in[3];
    const float* conf       = (const float*)d_in[4];
    const float* Wt1 = (const float*)d_in[5];
    const float* bt1 = (const float*)d_in[6];
    const float* Wt2 = (const float*)d_in[7];
    const float* bt2 = (const float*)d_in[8];
    const float* Ws1 = (const float*)d_in[9];
    const float* bs1 = (const float*)d_in[10];
    const float* Ws2 = (const float*)d_in[11];
    const float* bs2 = (const float*)d_in[12];
    const int*   perms = (const int*)d_in[13];
    float* out = (float*)d_out;

    // Pure queries (no stream work, no allocation) — graph-capture safe.
    float *H, *ht, *tt, *hs, *ts;
    cudaGetSymbolAddress((void**)&H,  g_H);
    cudaGetSymbolAddress((void**)&ht, g_ht);
    cudaGetSymbolAddress((void**)&tt, g_tt);
    cudaGetSymbolAddress((void**)&hs, g_hs);
    cudaGetSymbolAddress((void**)&ts, g_ts);

    const dim3 blk(256);
    const dim3 gT1(768 / BN, MROWS / BM);   // N=768
    const dim3 gT2(256 / BN, MROWS / BM);   // N=256

    // text: head
    gemm_bias_kernel<true ><<<gT1, blk>>>(head_text, Wt1, bt1, H,  MROWS, 768, 768);
    gemm_bias_kernel<false><<<gT2, blk>>>(H,         Wt2, bt2, ht, MROWS, 256, 768);
    // text: tail
    gemm_bias_kernel<true ><<<gT1, blk>>>(tail_text, Wt1, bt1, H,  MROWS, 768, 768);
    gemm_bias_kernel<false><<<gT2, blk>>>(H,         Wt2, bt2, tt, MROWS, 256, 768);
    // struc: head
    gemm_bias_kernel<true ><<<gT2, blk>>>(head_struc, Ws1, bs1, H,  MROWS, 256, 256);
    gemm_bias_kernel<false><<<gT2, blk>>>(H,          Ws2, bs2, hs, MROWS, 256, 256);
    // struc: tail
    gemm_bias_kernel<true ><<<gT2, blk>>>(tail_struc, Ws1, bs1, H,  MROWS, 256, 256);
    gemm_bias_kernel<false><<<gT2, blk>>>(H,          Ws2, bs2, ts, MROWS, 256, 256);

    // per-slot stats for both pairs
    stats_kernel<<<MROWS / 8, blk>>>(0);   // (ht, ts)
    stats_kernel<<<MROWS / 8, blk>>>(1);   // (tt, hs)

    // branch negatives + pos sims: one warp per (branch, row)
    branch_kernel<<<2 * BATCH / 8, blk>>>(perms);

    // outputs
    score_loss_kernel<<<64, blk>>>(conf, out);
    loss_final_kernel<<<1, 64>>>(out, 64);
    logits_kernel<<<4096, blk>>>(out);
}

// round 8
// speedup vs baseline: 1.7178x; 1.7178x over previous
#include <cuda_runtime.h>
#include <cuda_bf16.h>
#include <cstdint>

// ---------------------------------------------------------------------------
// Problem constants
// ---------------------------------------------------------------------------
#define BATCH    16384
#define MROWS    (BATCH * 3)
#define EMB      256
#define ROW      768
#define EPS      1e-8f

// ---------------------------------------------------------------------------
// Scratch (device globals; no allocation allowed)
// ---------------------------------------------------------------------------
__device__ __align__(16) float g_H [(size_t)MROWS * 768];
__device__ __align__(16) float g_ht[(size_t)MROWS * EMB];
__device__ __align__(16) float g_tt[(size_t)MROWS * EMB];
__device__ __align__(16) float g_hs[(size_t)MROWS * EMB];
__device__ __align__(16) float g_ts[(size_t)MROWS * EMB];
__device__ float g_dts[2][MROWS];
__device__ float g_qa [2][MROWS];
__device__ float g_qb [2][MROWS];
__device__ float g_P  [2 * BATCH];
__device__ float g_Ng [2 * BATCH];
__device__ float g_partial[64];

// Pre-converted weights: transposed [N][K] (K-major), bf16 hi/lo split
__device__ __align__(16) __nv_bfloat16 g_Wt1h[768 * 768], g_Wt1l[768 * 768];
__device__ __align__(16) __nv_bfloat16 g_Wt2h[256 * 768], g_Wt2l[256 * 768];
__device__ __align__(16) __nv_bfloat16 g_Ws1h[256 * 256], g_Ws1l[256 * 256];
__device__ __align__(16) __nv_bfloat16 g_Ws2h[256 * 256], g_Ws2l[256 * 256];

// ---------------------------------------------------------------------------
// mma.sync helper (baseline PTX, sm_80+; compiles for sm_103 non-a target)
// ---------------------------------------------------------------------------
__device__ __forceinline__ void mma16816(float* c, const uint32_t* a, const uint32_t* b) {
    asm volatile(
        "mma.sync.aligned.m16n8k16.row.col.f32.bf16.bf16.f32 "
        "{%0,%1,%2,%3}, {%4,%5,%6,%7}, {%8,%9}, {%0,%1,%2,%3};"
        : "+f"(c[0]), "+f"(c[1]), "+f"(c[2]), "+f"(c[3])
        : "r"(a[0]), "r"(a[1]), "r"(a[2]), "r"(a[3]), "r"(b[0]), "r"(b[1]));
}

// ---------------------------------------------------------------------------
// Weight pre-convert: W[K][N] fp32 -> transposed hiT/loT [N][K] bf16
// ---------------------------------------------------------------------------
__global__ void convert_w_kernel(const float* __restrict__ W,
                                 __nv_bfloat16* __restrict__ hiT,
                                 __nv_bfloat16* __restrict__ loT,
                                 int K, int N) {
    int idx = blockIdx.x * blockDim.x + threadIdx.x;
    if (idx >= K * N) return;
    int k = idx / N, n = idx % N;
    float f = W[idx];
    __nv_bfloat16 h = __float2bfloat16(f);
    float r = f - __bfloat162float(h);
    hiT[(size_t)n * K + k] = h;
    loT[(size_t)n * K + k] = __float2bfloat16(r);
}

// ---------------------------------------------------------------------------
// HMMA GEMM: C[MROWS,N] = act(A[MROWS,K] @ W[K,N] + bias)
// W as transposed bf16 hi/lo [N][K]. CTA tile 128x128, 8 warps (64x32 each),
// K-chunk 32 fp32 cols, bf16 3-pass split, double-buffered smem + reg prefetch.
// smem rows padded to 40 bf16 (stride 20 words -> conflict-free fragments).
// ---------------------------------------------------------------------------
#define LDS 40
#define TSZ (128 * LDS)                 // one tile (elems)
#define STAGE (4 * TSZ)                 // Ah|Al|Bh|Bl (elems)
#define SMEM_MM (2 * STAGE * 2)         // bytes = 81920

template <int N, int K, bool RELU>
__global__ void __launch_bounds__(256, 2)
mm_gemm_kernel(const float* __restrict__ A,
               const __nv_bfloat16* __restrict__ BhT,
               const __nv_bfloat16* __restrict__ BlT,
               const float* __restrict__ bias,
               float* __restrict__ C) {
    extern __shared__ __nv_bfloat16 sm[];
    const int tid = threadIdx.x;
    const int wid = tid >> 5, lane = tid & 31;
    const int g = lane >> 2, q = lane & 3;       // fragment quad coords
    const int wm = wid & 1, wn = wid >> 1;       // 2x4 warp grid
    const int m0 = blockIdx.y * 128;
    const int n0 = blockIdx.x * 128;
    constexpr int NCH = K / 32;

    // loader coords
    const int arow = tid >> 1, acb = (tid & 1) * 16;  // A: 2 thr/row, 16 floats
    const int brow = tid >> 1, bq  = (tid & 1) * 2;   // B: 2 thr/row, 2 uint4 each

    float cr[4][4][4];
#pragma unroll
    for (int i = 0; i < 4; i++)
#pragma unroll
        for (int j = 0; j < 4; j++)
#pragma unroll
            for (int k = 0; k < 4; k++) cr[i][j][k] = 0.f;

    float4 pav[4];
    uint4  pbh[2], pbl[2];

    // ---- prologue: fetch chunk 0 and stage into buffer 0 ----
    {
        const float* ap = A + (size_t)(m0 + arow) * K + acb;
#pragma unroll
        for (int j = 0; j < 4; j++) pav[j] = *(const float4*)(ap + j * 4);
        const uint4* bh = (const uint4*)(BhT + (size_t)(n0 + brow) * K);
        const uint4* bl = (const uint4*)(BlT + (size_t)(n0 + brow) * K);
        pbh[0] = bh[bq]; pbh[1] = bh[bq + 1];
        pbl[0] = bl[bq]; pbl[1] = bl[bq + 1];
    }
    {
        __nv_bfloat16* Ah = sm;
        __nv_bfloat16* Al = sm + TSZ;
        __nv_bfloat16* Bh = sm + 2 * TSZ;
        __nv_bfloat16* Bl = sm + 3 * TSZ;
#pragma unroll
        for (int j = 0; j < 4; j++) {
            float4 v = pav[j];
            float hx = __bfloat162float(__float2bfloat16(v.x));
            float hy = __bfloat162float(__float2bfloat16(v.y));
            float hz = __bfloat162float(__float2bfloat16(v.z));
            float hw = __bfloat162float(__float2bfloat16(v.w));
            int o = arow * LDS + acb + j * 4;
            *(__nv_bfloat162*)(Ah + o)     = __floats2bfloat162_rn(v.x, v.y);
            *(__nv_bfloat162*)(Ah + o + 2) = __floats2bfloat162_rn(v.z, v.w);
            *(__nv_bfloat162*)(Al + o)     = __floats2bfloat162_rn(v.x - hx, v.y - hy);
            *(__nv_bfloat162*)(Al + o + 2) = __floats2bfloat162_rn(v.z - hz, v.w - hw);
        }
        int bo = brow * LDS + bq * 8;
        *(uint4*)(Bh + bo)     = pbh[0];
        *(uint4*)(Bh + bo + 8) = pbh[1];
        *(uint4*)(Bl + bo)     = pbl[0];
        *(uint4*)(Bl + bo + 8) = pbl[1];
    }
    __syncthreads();

    for (int c = 0; c < NCH; c++) {
        const int buf = c & 1;
        // prefetch next chunk into registers
        if (c + 1 < NCH) {
            const float* ap = A + (size_t)(m0 + arow) * K + (c + 1) * 32 + acb;
#pragma unroll
            for (int j = 0; j < 4; j++) pav[j] = *(const float4*)(ap + j * 4);
            const uint4* bh = (const uint4*)(BhT + (size_t)(n0 + brow) * K + (c + 1) * 32);
            const uint4* bl = (const uint4*)(BlT + (size_t)(n0 + brow) * K + (c + 1) * 32);
            pbh[0] = bh[bq]; pbh[1] = bh[bq + 1];
            pbl[0] = bl[bq]; pbl[1] = bl[bq + 1];
        }

        // compute on current buffer: 3 passes (AhBh, AhBl, AlBh) x 2 k16 steps
        {
            const __nv_bfloat16* base = sm + buf * STAGE;
#pragma unroll
            for (int p = 0; p < 3; p++) {
                const __nv_bfloat16* As = base + ((p == 2) ? TSZ : 0);
                const __nv_bfloat16* Bs = base + ((p == 1) ? 3 * TSZ : 2 * TSZ);
#pragma unroll
                for (int s = 0; s < 2; s++) {
                    uint32_t bf[4][2];
#pragma unroll
                    for (int j = 0; j < 4; j++) {
                        const __nv_bfloat16* bp = Bs + (wn * 32 + j * 8 + g) * LDS + s * 16 + q * 2;
                        bf[j][0] = *(const uint32_t*)bp;
                        bf[j][1] = *(const uint32_t*)(bp + 8);
                    }
#pragma unroll
                    for (int i = 0; i < 4; i++) {
                        const __nv_bfloat16* apt = As + (wm * 64 + i * 16 + g) * LDS + s * 16 + q * 2;
                        uint32_t af[4];
                        af[0] = *(const uint32_t*)apt;
                        af[1] = *(const uint32_t*)(apt + 8 * LDS);
                        af[2] = *(const uint32_t*)(apt + 8);
                        af[3] = *(const uint32_t*)(apt + 8 * LDS + 8);
#pragma unroll
                        for (int j = 0; j < 4; j++) mma16816(cr[i][j], af, bf[j]);
                    }
                }
            }
        }

        // stage prefetched chunk into the other buffer
        if (c + 1 < NCH) {
            __nv_bfloat16* nb = sm + (buf ^ 1) * STAGE;
            __nv_bfloat16* Ah = nb;
            __nv_bfloat16* Al = nb + TSZ;
            __nv_bfloat16* Bh = nb + 2 * TSZ;
            __nv_bfloat16* Bl = nb + 3 * TSZ;
#pragma unroll
            for (int j = 0; j < 4; j++) {
                float4 v = pav[j];
                float hx = __bfloat162float(__float2bfloat16(v.x));
                float hy = __bfloat162float(__float2bfloat16(v.y));
                float hz = __bfloat162float(__float2bfloat16(v.z));
                float hw = __bfloat162float(__float2bfloat16(v.w));
                int o = arow * LDS + acb + j * 4;
                *(__nv_bfloat162*)(Ah + o)     = __floats2bfloat162_rn(v.x, v.y);
                *(__nv_bfloat162*)(Ah + o + 2) = __floats2bfloat162_rn(v.z, v.w);
                *(__nv_bfloat162*)(Al + o)     = __floats2bfloat162_rn(v.x - hx, v.y - hy);
                *(__nv_bfloat162*)(Al + o + 2) = __floats2bfloat162_rn(v.z - hz, v.w - hw);
            }
            int bo = brow * LDS + bq * 8;
            *(uint4*)(Bh + bo)     = pbh[0];
            *(uint4*)(Bh + bo + 8) = pbh[1];
            *(uint4*)(Bl + bo)     = pbl[0];
            *(uint4*)(Bl + bo + 8) = pbl[1];
            __syncthreads();
        }
    }

    // ---- epilogue: bias (+relu), store float2 pairs ----
#pragma unroll
    for (int i = 0; i < 4; i++) {
        const int r0 = m0 + wm * 64 + i * 16 + g;
#pragma unroll
        for (int j = 0; j < 4; j++) {
            const int cb = n0 + wn * 32 + j * 8 + q * 2;
            float b0 = __ldg(bias + cb), b1 = __ldg(bias + cb + 1);
            float v0 = cr[i][j][0] + b0, v1 = cr[i][j][1] + b1;
            float v2 = cr[i][j][2] + b0, v3 = cr[i][j][3] + b1;
            if (RELU) {
                v0 = fmaxf(v0, 0.f); v1 = fmaxf(v1, 0.f);
                v2 = fmaxf(v2, 0.f); v3 = fmaxf(v3, 0.f);
            }
            *(float2*)(C + (size_t)r0 * N + cb)       = make_float2(v0, v1);
            *(float2*)(C + (size_t)(r0 + 8) * N + cb) = make_float2(v2, v3);
        }
    }
}

// ---------------------------------------------------------------------------
// Epilogue helpers
// ---------------------------------------------------------------------------
__device__ __forceinline__ float dot4(float4 a, float4 b) {
    return a.x * b.x + a.y * b.y + a.z * b.z + a.w * b.w;
}
__device__ __forceinline__ float wred(float v) {
#pragma unroll
    for (int o = 16; o; o >>= 1) v += __shfl_xor_sync(0xFFFFFFFFu, v, o);
    return v;
}
__device__ __forceinline__ float cosv(float d, float na2, float nb2) {
    float na = fmaxf(sqrtf(na2), EPS);
    float nb = fmaxf(sqrtf(nb2), EPS);
    return d / (na * nb);
}

// ---------------------------------------------------------------------------
// Per-(row,slot) stats
// ---------------------------------------------------------------------------
__global__ void __launch_bounds__(256) stats_kernel(int j) {
    const int wg = (blockIdx.x * blockDim.x + threadIdx.x) >> 5;
    if (wg >= MROWS) return;
    const int lane = threadIdx.x & 31;
    const float* T = j ? g_tt : g_ht;
    const float* S = j ? g_hs : g_ts;
    const float* t = T + (size_t)wg * EMB + lane * 4;
    const float* s = S + (size_t)wg * EMB + lane * 4;
    float d = 0.f, a = 0.f, b = 0.f;
#pragma unroll
    for (int w = 0; w < 2; w++) {
        float4 tv = *(const float4*)(t + w * 128);
        float4 sv = *(const float4*)(s + w * 128);
        d += dot4(tv, sv);
        a += dot4(tv, tv);
        b += dot4(sv, sv);
    }
    d = wred(d); a = wred(a); b = wred(b);
    if (lane == 0) {
        g_dts[j][wg] = d;
        g_qa[j][wg]  = a;
        g_qb[j][wg]  = b;
    }
}

// ---------------------------------------------------------------------------
// Branch kernel: one warp per (branch j, row b)
// ---------------------------------------------------------------------------
__global__ void __launch_bounds__(256) branch_kernel(const int* __restrict__ perms) {
    const int wg = (blockIdx.x * blockDim.x + threadIdx.x) >> 5;
    if (wg >= 2 * BATCH) return;
    const int lane = threadIdx.x & 31;
    const int j = wg >> 14;
    const int b = wg & (BATCH - 1);

    const float* T = j ? g_tt : g_ht;
    const float* S = j ? g_hs : g_ts;
    const float* dts = g_dts[j];
    const float* qa3 = g_qa[j];
    const float* qb3 = g_qb[j];
    const int* p = perms + j * 8 * BATCH;

    float4 trv[6], srv[6];
    const float* trow = T + (size_t)b * ROW + lane * 4;
    const float* srow = S + (size_t)b * ROW + lane * 4;
#pragma unroll
    for (int w = 0; w < 6; w++) {
        trv[w] = *(const float4*)(trow + w * 128);
        srv[w] = *(const float4*)(srow + w * 128);
    }
    float dp = 0.f, qa = 0.f, qb = 0.f;
#pragma unroll
    for (int w = 0; w < 6; w++) {
        dp += dot4(trv[w], srv[w]);
        qa += dot4(trv[w], trv[w]);
        qb += dot4(srv[w], srv[w]);
    }
    dp = wred(dp); qa = wred(qa); qb = wred(qb);

    const int p4 = p[4 * BATCH + b], p5 = p[5 * BATCH + b];
    const int p6 = p[6 * BATCH + b], p7 = p[7 * BATCH + b];
    const float* r4 = T + (size_t)p4 * ROW + lane * 4;
    const float* r5 = S + (size_t)p5 * ROW + lane * 4;
    const float* r6 = T + (size_t)p6 * ROW + lane * 4;
    const float* r7 = S + (size_t)p7 * ROW + lane * 4;
    float d4 = 0.f, d5 = 0.f, d6 = 0.f, d7 = 0.f;
#pragma unroll
    for (int w = 0; w < 6; w++) {
        d4 += dot4(*(const float4*)(r4 + w * 128), srv[w]);
        d6 += dot4(*(const float4*)(r6 + w * 128), srv[w]);
        d5 += dot4(*(const float4*)(r5 + w * 128), trv[w]);
        d7 += dot4(*(const float4*)(r7 + w * 128), trv[w]);
    }
    d4 = wred(d4); d5 = wred(d5); d6 = wred(d6); d7 = wred(d7);

    if (lane == 0) {
        const int p0 = p[b], p1 = p[BATCH + b];
        const int p2 = p[2 * BATCH + b], p3 = p[3 * BATCH + b];
        const int b3 = b * 3;
        const float dt0 = dts[b3], dt1 = dts[b3 + 1], dt2 = dts[b3 + 2];
        const float a0 = qa3[b3], a1 = qa3[b3 + 1], a2 = qa3[b3 + 2];
        const float q0 = qb3[b3], q1 = qb3[b3 + 1], q2 = qb3[b3 + 2];

        float neg = 0.f;
        neg += expf(cosv(dt0 + dt1 + dts[p0 * 3 + 2],
                         a0 + a1 + qa3[p0 * 3 + 2],
                         q0 + q1 + qb3[p0 * 3 + 2]));
        neg += expf(cosv(dts[p1 * 3] + dt1 + dt2,
                         qa3[p1 * 3] + a1 + a2,
                         qb3[p1 * 3] + q1 + q2));
        neg += expf(cosv(dt0 + dt1 + dts[p2 * 3 + 2],
                         a0 + a1 + qa3[p2 * 3 + 2],
                         q0 + q1 + qb3[p2 * 3 + 2]));
        neg += expf(cosv(dts[p3 * 3] + dt1 + dt2,
                         qa3[p3 * 3] + a1 + a2,
                         qb3[p3 * 3] + q1 + q2));
        neg += expf(cosv(d4, qa3[p4 * 3] + qa3[p4 * 3 + 1] + qa3[p4 * 3 + 2], qb));
        neg += expf(cosv(d5, qa, qb3[p5 * 3] + qb3[p5 * 3 + 1] + qb3[p5 * 3 + 2]));
        neg += expf(cosv(d6, qa3[p6 * 3] + qa3[p6 * 3 + 1] + qa3[p6 * 3 + 2], qb));
        neg += expf(cosv(d7, qa, qb3[p7 * 3] + qb3[p7 * 3 + 1] + qb3[p7 * 3 + 2]));

        g_P[wg]  = expf(cosv(dp, qa, qb));
        g_Ng[wg] = neg;
    }
}

// ---------------------------------------------------------------------------
// score + deterministic two-stage loss reduction
// ---------------------------------------------------------------------------
__global__ void __launch_bounds__(256) score_loss_kernel(const float* __restrict__ conf,
                                                         float* __restrict__ out) {
    __shared__ float smr[256];
    float local = 0.f;
    for (int b = blockIdx.x * 256 + threadIdx.x; b < BATCH; b += 256 * gridDim.x) {
        float p0 = g_P[b],         n0 = g_Ng[b];
        float p1 = g_P[BATCH + b], n1 = g_Ng[BATCH + b];
        out[1 + b] = -(p0 + p1);
        local += -conf[b] * (logf(p0 / (p0 + n0)) + logf(p1 / (p1 + n1)));
    }
    smr[threadIdx.x] = local;
    __syncthreads();
    for (int s = 128; s; s >>= 1) {
        if (threadIdx.x < s) smr[threadIdx.x] += smr[threadIdx.x + s];
        __syncthreads();
    }
    if (threadIdx.x == 0) g_partial[blockIdx.x] = smr[0];
}

__global__ void loss_final_kernel(float* __restrict__ out, int nPart) {
    __shared__ float smr[64];
    const int t = threadIdx.x;
    smr[t] = (t < nPart) ? g_partial[t] : 0.f;
    __syncthreads();
    for (int s = 32; s; s >>= 1) {
        if (t < s) smr[t] += smr[t + s];
        __syncthreads();
    }
    if (t == 0) out[0] = smr[0] * (1.f / BATCH);
}

// ---------------------------------------------------------------------------
// logits output
// ---------------------------------------------------------------------------
__global__ void __launch_bounds__(256) logits_kernel(float* __restrict__ out) {
    const size_t n = (size_t)BATCH * ROW;
    float* otext  = out + 1 + BATCH;
    float* ostruc = otext + n;
    for (size_t i = blockIdx.x * (size_t)blockDim.x + threadIdx.x; i < n;
         i += (size_t)gridDim.x * blockDim.x) {
        otext[i]  = g_ht[i] + g_tt[i];
        ostruc[i] = g_hs[i] + g_ts[i];
    }
}

// ---------------------------------------------------------------------------
// Launch
// ---------------------------------------------------------------------------
extern "C" void kernel_launch(void* const* d_in, const int* in_sizes, int n_in,
                              void* d_out, int out_size) {
    const float* head_text  = (const float*)d_in[0];
    const float* tail_text  = (const float*)d_in[1];
    const float* head_struc = (const float*)d_in[2];
    const float* tail_struc = (const float*)d_in[3];
    const float* conf       = (const float*)d_in[4];
    const float* Wt1 = (const float*)d_in[5];
    const float* bt1 = (const float*)d_in[6];
    const float* Wt2 = (const float*)d_in[7];
    const float* bt2 = (const float*)d_in[8];
    const float* Ws1 = (const float*)d_in[9];
    const float* bs1 = (const float*)d_in[10];
    const float* Ws2 = (const float*)d_in[11];
    const float* bs2 = (const float*)d_in[12];
    const int*   perms = (const int*)d_in[13];
    float* out = (float*)d_out;

    // Pure queries — graph-capture safe.
    float *H, *ht, *tt, *hs, *ts;
    cudaGetSymbolAddress((void**)&H,  g_H);
    cudaGetSymbolAddress((void**)&ht, g_ht);
    cudaGetSymbolAddress((void**)&tt, g_tt);
    cudaGetSymbolAddress((void**)&hs, g_hs);
    cudaGetSymbolAddress((void**)&ts, g_ts);
    __nv_bfloat16 *wt1h, *wt1l, *wt2h, *wt2l, *ws1h, *ws1l, *ws2h, *ws2l;
    cudaGetSymbolAddress((void**)&wt1h, g_Wt1h);
    cudaGetSymbolAddress((void**)&wt1l, g_Wt1l);
    cudaGetSymbolAddress((void**)&wt2h, g_Wt2h);
    cudaGetSymbolAddress((void**)&wt2l, g_Wt2l);
    cudaGetSymbolAddress((void**)&ws1h, g_Ws1h);
    cudaGetSymbolAddress((void**)&ws1l, g_Ws1l);
    cudaGetSymbolAddress((void**)&ws2h, g_Ws2h);
    cudaGetSymbolAddress((void**)&ws2l, g_Ws2l);

    // Raise dynamic smem limits (idempotent host-side attribute).
    cudaFuncSetAttribute(mm_gemm_kernel<768, 768, true >, cudaFuncAttributeMaxDynamicSharedMemorySize, SMEM_MM);
    cudaFuncSetAttribute(mm_gemm_kernel<256, 768, false>, cudaFuncAttributeMaxDynamicSharedMemorySize, SMEM_MM);
    cudaFuncSetAttribute(mm_gemm_kernel<256, 256, true >, cudaFuncAttributeMaxDynamicSharedMemorySize, SMEM_MM);
    cudaFuncSetAttribute(mm_gemm_kernel<256, 256, false>, cudaFuncAttributeMaxDynamicSharedMemorySize, SMEM_MM);

    const dim3 blk(256);

    // weight pre-convert (tiny)
    convert_w_kernel<<<(768 * 768 + 255) / 256, blk>>>(Wt1, wt1h, wt1l, 768, 768);
    convert_w_kernel<<<(768 * 256 + 255) / 256, blk>>>(Wt2, wt2h, wt2l, 768, 256);
    convert_w_kernel<<<(256 * 256 + 255) / 256, blk>>>(Ws1, ws1h, ws1l, 256, 256);
    convert_w_kernel<<<(256 * 256 + 255) / 256, blk>>>(Ws2, ws2h, ws2l, 256, 256);

    const dim3 gT1(768 / 128, MROWS / 128);   // (6, 384)
    const dim3 gT2(256 / 128, MROWS / 128);   // (2, 384)

    // text: head
    mm_gemm_kernel<768, 768, true ><<<gT1, blk, SMEM_MM>>>(head_text, wt1h, wt1l, bt1, H);
    mm_gemm_kernel<256, 768, false><<<gT2, blk, SMEM_MM>>>(H,         wt2h, wt2l, bt2, ht);
    // text: tail
    mm_gemm_kernel<768, 768, true ><<<gT1, blk, SMEM_MM>>>(tail_text, wt1h, wt1l, bt1, H);
    mm_gemm_kernel<256, 768, false><<<gT2, blk, SMEM_MM>>>(H,         wt2h, wt2l, bt2, tt);
    // struc: head
    mm_gemm_kernel<256, 256, true ><<<gT2, blk, SMEM_MM>>>(head_struc, ws1h, ws1l, bs1, H);
    mm_gemm_kernel<256, 256, false><<<gT2, blk, SMEM_MM>>>(H,          ws2h, ws2l, bs2, hs);
    // struc: tail
    mm_gemm_kernel<256, 256, true ><<<gT2, blk, SMEM_MM>>>(tail_struc, ws1h, ws1l, bs1, H);
    mm_gemm_kernel<256, 256, false><<<gT2, blk, SMEM_MM>>>(H,          ws2h, ws2l, bs2, ts);

    // per-slot stats for both pairs
    stats_kernel<<<MROWS / 8, blk>>>(0);
    stats_kernel<<<MROWS / 8, blk>>>(1);

    // branch negatives + pos sims
    branch_kernel<<<2 * BATCH / 8, blk>>>(perms);

    // outputs
    score_loss_kernel<<<64, blk>>>(conf, out);
    loss_final_kernel<<<1, 64>>>(out, 64);
    logits_kernel<<<4096, blk>>>(out);
}

// round 11
// speedup vs baseline: 2.1906x; 1.2752x over previous
#include <cuda_runtime.h>
#include <cuda_bf16.h>
#include <cstdint>

// ---------------------------------------------------------------------------
// Problem constants
// ---------------------------------------------------------------------------
#define BATCH    16384
#define MROWS    (BATCH * 3)
#define EMB      256
#define ROW      768
#define EPS      1e-8f

// ---------------------------------------------------------------------------
// Scratch (device globals; no allocation allowed)
// ---------------------------------------------------------------------------
__device__ __align__(16) __nv_bfloat16 g_Ah[(size_t)MROWS * 768];   // input hi
__device__ __align__(16) __nv_bfloat16 g_Al[(size_t)MROWS * 768];   // input lo
__device__ __align__(16) __nv_bfloat16 g_Hh[(size_t)MROWS * 768];   // hidden hi
__device__ __align__(16) __nv_bfloat16 g_Hl[(size_t)MROWS * 768];   // hidden lo
__device__ __align__(16) float g_ht[(size_t)MROWS * EMB];
__device__ __align__(16) float g_tt[(size_t)MROWS * EMB];
__device__ __align__(16) float g_hs[(size_t)MROWS * EMB];
__device__ __align__(16) float g_ts[(size_t)MROWS * EMB];
__device__ float g_dts[2][MROWS];
__device__ float g_qa [2][MROWS];
__device__ float g_qb [2][MROWS];
__device__ float g_P  [2 * BATCH];
__device__ float g_Ng [2 * BATCH];
__device__ float g_partial[64];

// Pre-converted weights: transposed [N][K] (K-major), bf16 hi/lo split
__device__ __align__(16) __nv_bfloat16 g_Wt1h[768 * 768], g_Wt1l[768 * 768];
__device__ __align__(16) __nv_bfloat16 g_Wt2h[256 * 768], g_Wt2l[256 * 768];
__device__ __align__(16) __nv_bfloat16 g_Ws1h[256 * 256], g_Ws1l[256 * 256];
__device__ __align__(16) __nv_bfloat16 g_Ws2h[256 * 256], g_Ws2l[256 * 256];

// ---------------------------------------------------------------------------
// PTX helpers (all baseline sm_80-era; compile for non-'a' sm_103 target)
// ---------------------------------------------------------------------------
__device__ __forceinline__ uint32_t s2u(const void* p) {
    uint32_t a;
    asm("{ .reg .u64 t; cvta.to.shared.u64 t, %1; cvt.u32.u64 %0, t; }" : "=r"(a) : "l"(p));
    return a;
}

__device__ __forceinline__ void mma16816(float* c, const uint32_t* a, const uint32_t* b) {
    asm volatile(
        "mma.sync.aligned.m16n8k16.row.col.f32.bf16.bf16.f32 "
        "{%0,%1,%2,%3}, {%4,%5,%6,%7}, {%8,%9}, {%0,%1,%2,%3};"
        : "+f"(c[0]), "+f"(c[1]), "+f"(c[2]), "+f"(c[3])
        : "r"(a[0]), "r"(a[1]), "r"(a[2]), "r"(a[3]), "r"(b[0]), "r"(b[1]));
}

__device__ __forceinline__ void cpa16(uint32_t s, const void* g) {
    asm volatile("cp.async.cg.shared.global [%0], [%1], 16;" :: "r"(s), "l"(g));
}
#define CP_COMMIT() asm volatile("cp.async.commit_group;" ::: "memory")
#define CP_WAIT1()  asm volatile("cp.async.wait_group 1;" ::: "memory")
#define CP_WAIT0()  asm volatile("cp.async.wait_group 0;" ::: "memory")

// ---------------------------------------------------------------------------
// Weight pre-convert: W[K][N] fp32 -> transposed hiT/loT [N][K] bf16
// ---------------------------------------------------------------------------
__global__ void convert_w_kernel(const float* __restrict__ W,
                                 __nv_bfloat16* __restrict__ hiT,
                                 __nv_bfloat16* __restrict__ loT,
                                 int K, int N) {
    int idx = blockIdx.x * blockDim.x + threadIdx.x;
    if (idx >= K * N) return;
    int k = idx / N, n = idx % N;
    float f = W[idx];
    __nv_bfloat16 h = __float2bfloat16(f);
    float r = f - __bfloat162float(h);
    hiT[(size_t)n * K + k] = h;
    loT[(size_t)n * K + k] = __float2bfloat16(r);
}

// ---------------------------------------------------------------------------
// Activation pre-convert: X[M*K] fp32 -> Ah/Al bf16 (same row-major layout)
// ---------------------------------------------------------------------------
__global__ void __launch_bounds__(256) convert_a_kernel(const float* __restrict__ X,
                                 __nv_bfloat16* __restrict__ Ah,
                                 __nv_bfloat16* __restrict__ Al, int n4) {
    int i = blockIdx.x * blockDim.x + threadIdx.x;
    if (i >= n4) return;
    float4 v = ((const float4*)X)[i];
    __nv_bfloat16 hx = __float2bfloat16(v.x), hy = __float2bfloat16(v.y);
    __nv_bfloat16 hz = __float2bfloat16(v.z), hw = __float2bfloat16(v.w);
    ((__nv_bfloat162*)Ah)[2 * i]     = __halves2bfloat162(hx, hy);
    ((__nv_bfloat162*)Ah)[2 * i + 1] = __halves2bfloat162(hz, hw);
    ((__nv_bfloat162*)Al)[2 * i]     = __floats2bfloat162_rn(v.x - __bfloat162float(hx),
                                                             v.y - __bfloat162float(hy));
    ((__nv_bfloat162*)Al)[2 * i + 1] = __floats2bfloat162_rn(v.z - __bfloat162float(hz),
                                                             v.w - __bfloat162float(hw));
}

// ---------------------------------------------------------------------------
// HMMA GEMM, all-bf16 operands, cp.async 2-stage pipeline.
// C = act(A @ W + bias); A as (Ah,Al) [M][K] bf16; W as (BhT,BlT) [N][K] bf16.
// CTA tile 128x128, 8 warps (64x32), K-chunk 32. 3-pass: AhBh + AhBl + AlBh.
// OUTSPLIT: write C as bf16 hi/lo pair (for hidden layer); else fp32.
// smem rows padded to 40 bf16 -> conflict-free fragment loads.
// ---------------------------------------------------------------------------
#define LDSW 40
#define TSZE (128 * LDSW)               // elems per tile = 5120
#define STAGE_E (4 * TSZE)              // Ah|Al|Bh|Bl = 20480 elems
#define SMEM_MM (2 * STAGE_E * 2)       // 81920 bytes

template <int N, int K, bool OUTSPLIT, bool RELU>
__global__ void __launch_bounds__(256, 2)
mm2_kernel(const __nv_bfloat16* __restrict__ Ahp, const __nv_bfloat16* __restrict__ Alp,
           const __nv_bfloat16* __restrict__ BhT, const __nv_bfloat16* __restrict__ BlT,
           const float* __restrict__ bias,
           float* __restrict__ C,
           __nv_bfloat16* __restrict__ Ch, __nv_bfloat16* __restrict__ Cl) {
    extern __shared__ __nv_bfloat16 sm[];
    const uint32_t smb = s2u(sm);
    const int tid = threadIdx.x;
    const int wid = tid >> 5, lane = tid & 31;
    const int g = lane >> 2, q = lane & 3;
    const int wm = wid & 1, wn = wid >> 1;
    const int m0 = blockIdx.y * 128;
    const int n0 = blockIdx.x * 128;
    constexpr int NCH = K / 32;

    float cr[4][4][4];
#pragma unroll
    for (int i = 0; i < 4; i++)
#pragma unroll
        for (int j = 0; j < 4; j++)
#pragma unroll
            for (int k = 0; k < 4; k++) cr[i][j][k] = 0.f;

    // cp.async one K-chunk (4 tiles of 128x32 bf16) into stage `buf`
    auto stage_load = [&](int buf, int c) {
        const uint32_t sb = smb + buf * (STAGE_E * 2);
        const __nv_bfloat16* src[4] = {Ahp, Alp, BhT, BlT};
#pragma unroll
        for (int t4 = 0; t4 < 4; t4++) {
            const __nv_bfloat16* sp = src[t4];
            const int r0g = (t4 < 2) ? m0 : n0;
#pragma unroll
            for (int rep = 0; rep < 2; rep++) {
                const int s = tid + rep * 256;
                const int row = s >> 2, sub = s & 3;
                cpa16(sb + (uint32_t)(t4 * TSZE + row * LDSW + sub * 8) * 2,
                      sp + (size_t)(r0g + row) * K + c * 32 + sub * 8);
            }
        }
        CP_COMMIT();
    };

    stage_load(0, 0);

    for (int c = 0; c < NCH; c++) {
        const int buf = c & 1;
        if (c + 1 < NCH) {
            stage_load(buf ^ 1, c + 1);
            CP_WAIT1();          // chunk c landed (1 group outstanding)
        } else {
            CP_WAIT0();
        }
        __syncthreads();

        // compute: 3 passes (AhBh, AhBl, AlBh) x 2 k16 steps
        const __nv_bfloat16* base = sm + buf * STAGE_E;
#pragma unroll
        for (int p = 0; p < 3; p++) {
            const __nv_bfloat16* As = base + ((p == 2) ? TSZE : 0);
            const __nv_bfloat16* Bs = base + ((p == 1) ? 3 * TSZE : 2 * TSZE);
#pragma unroll
            for (int s = 0; s < 2; s++) {
                uint32_t bf[4][2];
#pragma unroll
                for (int j = 0; j < 4; j++) {
                    const __nv_bfloat16* bp = Bs + (wn * 32 + j * 8 + g) * LDSW + s * 16 + q * 2;
                    bf[j][0] = *(const uint32_t*)bp;
                    bf[j][1] = *(const uint32_t*)(bp + 8);
                }
#pragma unroll
                for (int i = 0; i < 4; i++) {
                    const __nv_bfloat16* apt = As + (wm * 64 + i * 16 + g) * LDSW + s * 16 + q * 2;
                    uint32_t af[4];
                    af[0] = *(const uint32_t*)apt;
                    af[1] = *(const uint32_t*)(apt + 8 * LDSW);
                    af[2] = *(const uint32_t*)(apt + 8);
                    af[3] = *(const uint32_t*)(apt + 8 * LDSW + 8);
#pragma unroll
                    for (int j = 0; j < 4; j++) mma16816(cr[i][j], af, bf[j]);
                }
            }
        }
        __syncthreads();   // all warps done with `buf` before next iter overwrites it
    }

    // ---- epilogue ----
#pragma unroll
    for (int i = 0; i < 4; i++) {
        const int r0 = m0 + wm * 64 + i * 16 + g;
#pragma unroll
        for (int j = 0; j < 4; j++) {
            const int cb = n0 + wn * 32 + j * 8 + q * 2;
            const float b0 = __ldg(bias + cb), b1 = __ldg(bias + cb + 1);
            float v0 = cr[i][j][0] + b0, v1 = cr[i][j][1] + b1;
            float v2 = cr[i][j][2] + b0, v3 = cr[i][j][3] + b1;
            if (RELU) {
                v0 = fmaxf(v0, 0.f); v1 = fmaxf(v1, 0.f);
                v2 = fmaxf(v2, 0.f); v3 = fmaxf(v3, 0.f);
            }
            if constexpr (OUTSPLIT) {
                __nv_bfloat16 h0 = __float2bfloat16(v0), h1 = __float2bfloat16(v1);
                __nv_bfloat16 h2 = __float2bfloat16(v2), h3 = __float2bfloat16(v3);
                *(__nv_bfloat162*)(Ch + (size_t)r0 * N + cb) = __halves2bfloat162(h0, h1);
                *(__nv_bfloat162*)(Cl + (size_t)r0 * N + cb) =
                    __floats2bfloat162_rn(v0 - __bfloat162float(h0), v1 - __bfloat162float(h1));
                *(__nv_bfloat162*)(Ch + (size_t)(r0 + 8) * N + cb) = __halves2bfloat162(h2, h3);
                *(__nv_bfloat162*)(Cl + (size_t)(r0 + 8) * N + cb) =
                    __floats2bfloat162_rn(v2 - __bfloat162float(h2), v3 - __bfloat162float(h3));
            } else {
                *(float2*)(C + (size_t)r0 * N + cb)       = make_float2(v0, v1);
                *(float2*)(C + (size_t)(r0 + 8) * N + cb) = make_float2(v2, v3);
            }
        }
    }
}

// ---------------------------------------------------------------------------
// Epilogue helpers
// ---------------------------------------------------------------------------
__device__ __forceinline__ float dot4(float4 a, float4 b) {
    return a.x * b.x + a.y * b.y + a.z * b.z + a.w * b.w;
}
__device__ __forceinline__ float wred(float v) {
#pragma unroll
    for (int o = 16; o; o >>= 1) v += __shfl_xor_sync(0xFFFFFFFFu, v, o);
    return v;
}
__device__ __forceinline__ float cosv(float d, float na2, float nb2) {
    float na = fmaxf(sqrtf(na2), EPS);
    float nb = fmaxf(sqrtf(nb2), EPS);
    return d / (na * nb);
}

// ---------------------------------------------------------------------------
// Per-(row,slot) stats
// ---------------------------------------------------------------------------
__global__ void __launch_bounds__(256) stats_kernel(int j) {
    const int wg = (blockIdx.x * blockDim.x + threadIdx.x) >> 5;
    if (wg >= MROWS) return;
    const int lane = threadIdx.x & 31;
    const float* T = j ? g_tt : g_ht;
    const float* S = j ? g_hs : g_ts;
    const float* t = T + (size_t)wg * EMB + lane * 4;
    const float* s = S + (size_t)wg * EMB + lane * 4;
    float d = 0.f, a = 0.f, b = 0.f;
#pragma unroll
    for (int w = 0; w < 2; w++) {
        float4 tv = *(const float4*)(t + w * 128);
        float4 sv = *(const float4*)(s + w * 128);
        d += dot4(tv, sv);
        a += dot4(tv, tv);
        b += dot4(sv, sv);
    }
    d = wred(d); a = wred(a); b = wred(b);
    if (lane == 0) {
        g_dts[j][wg] = d;
        g_qa[j][wg]  = a;
        g_qb[j][wg]  = b;
    }
}

// ---------------------------------------------------------------------------
// Branch kernel: one warp per (branch j, row b)
// ---------------------------------------------------------------------------
__global__ void __launch_bounds__(256) branch_kernel(const int* __restrict__ perms) {
    const int wg = (blockIdx.x * blockDim.x + threadIdx.x) >> 5;
    if (wg >= 2 * BATCH) return;
    const int lane = threadIdx.x & 31;
    const int j = wg >> 14;
    const int b = wg & (BATCH - 1);

    const float* T = j ? g_tt : g_ht;
    const float* S = j ? g_hs : g_ts;
    const float* dts = g_dts[j];
    const float* qa3 = g_qa[j];
    const float* qb3 = g_qb[j];
    const int* p = perms + j * 8 * BATCH;

    float4 trv[6], srv[6];
    const float* trow = T + (size_t)b * ROW + lane * 4;
    const float* srow = S + (size_t)b * ROW + lane * 4;
#pragma unroll
    for (int w = 0; w < 6; w++) {
        trv[w] = *(const float4*)(trow + w * 128);
        srv[w] = *(const float4*)(srow + w * 128);
    }
    float dp = 0.f, qa = 0.f, qb = 0.f;
#pragma unroll
    for (int w = 0; w < 6; w++) {
        dp += dot4(trv[w], srv[w]);
        qa += dot4(trv[w], trv[w]);
        qb += dot4(srv[w], srv[w]);
    }
    dp = wred(dp); qa = wred(qa); qb = wred(qb);

    const int p4 = p[4 * BATCH + b], p5 = p[5 * BATCH + b];
    const int p6 = p[6 * BATCH + b], p7 = p[7 * BATCH + b];
    const float* r4 = T + (size_t)p4 * ROW + lane * 4;
    const float* r5 = S + (size_t)p5 * ROW + lane * 4;
    const float* r6 = T + (size_t)p6 * ROW + lane * 4;
    const float* r7 = S + (size_t)p7 * ROW + lane * 4;
    float d4 = 0.f, d5 = 0.f, d6 = 0.f, d7 = 0.f;
#pragma unroll
    for (int w = 0; w < 6; w++) {
        d4 += dot4(*(const float4*)(r4 + w * 128), srv[w]);
        d6 += dot4(*(const float4*)(r6 + w * 128), srv[w]);
        d5 += dot4(*(const float4*)(r5 + w * 128), trv[w]);
        d7 += dot4(*(const float4*)(r7 + w * 128), trv[w]);
    }
    d4 = wred(d4); d5 = wred(d5); d6 = wred(d6); d7 = wred(d7);

    if (lane == 0) {
        const int p0 = p[b], p1 = p[BATCH + b];
        const int p2 = p[2 * BATCH + b], p3 = p[3 * BATCH + b];
        const int b3 = b * 3;
        const float dt0 = dts[b3], dt1 = dts[b3 + 1], dt2 = dts[b3 + 2];
        const float a0 = qa3[b3], a1 = qa3[b3 + 1], a2 = qa3[b3 + 2];
        const float q0 = qb3[b3], q1 = qb3[b3 + 1], q2 = qb3[b3 + 2];

        float neg = 0.f;
        neg += expf(cosv(dt0 + dt1 + dts[p0 * 3 + 2],
                         a0 + a1 + qa3[p0 * 3 + 2],
                         q0 + q1 + qb3[p0 * 3 + 2]));
        neg += expf(cosv(dts[p1 * 3] + dt1 + dt2,
                         qa3[p1 * 3] + a1 + a2,
                         qb3[p1 * 3] + q1 + q2));
        neg += expf(cosv(dt0 + dt1 + dts[p2 * 3 + 2],
                         a0 + a1 + qa3[p2 * 3 + 2],
                         q0 + q1 + qb3[p2 * 3 + 2]));
        neg += expf(cosv(dts[p3 * 3] + dt1 + dt2,
                         qa3[p3 * 3] + a1 + a2,
                         qb3[p3 * 3] + q1 + q2));
        neg += expf(cosv(d4, qa3[p4 * 3] + qa3[p4 * 3 + 1] + qa3[p4 * 3 + 2], qb));
        neg += expf(cosv(d5, qa, qb3[p5 * 3] + qb3[p5 * 3 + 1] + qb3[p5 * 3 + 2]));
        neg += expf(cosv(d6, qa3[p6 * 3] + qa3[p6 * 3 + 1] + qa3[p6 * 3 + 2], qb));
        neg += expf(cosv(d7, qa, qb3[p7 * 3] + qb3[p7 * 3 + 1] + qb3[p7 * 3 + 2]));

        g_P[wg]  = expf(cosv(dp, qa, qb));
        g_Ng[wg] = neg;
    }
}

// ---------------------------------------------------------------------------
// score + deterministic two-stage loss reduction
// ---------------------------------------------------------------------------
__global__ void __launch_bounds__(256) score_loss_kernel(const float* __restrict__ conf,
                                                         float* __restrict__ out) {
    __shared__ float smr[256];
    float local = 0.f;
    for (int b = blockIdx.x * 256 + threadIdx.x; b < BATCH; b += 256 * gridDim.x) {
        float p0 = g_P[b],         n0 = g_Ng[b];
        float p1 = g_P[BATCH + b], n1 = g_Ng[BATCH + b];
        out[1 + b] = -(p0 + p1);
        local += -conf[b] * (logf(p0 / (p0 + n0)) + logf(p1 / (p1 + n1)));
    }
    smr[threadIdx.x] = local;
    __syncthreads();
    for (int s = 128; s; s >>= 1) {
        if (threadIdx.x < s) smr[threadIdx.x] += smr[threadIdx.x + s];
        __syncthreads();
    }
    if (threadIdx.x == 0) g_partial[blockIdx.x] = smr[0];
}

__global__ void loss_final_kernel(float* __restrict__ out, int nPart) {
    __shared__ float smr[64];
    const int t = threadIdx.x;
    smr[t] = (t < nPart) ? g_partial[t] : 0.f;
    __syncthreads();
    for (int s = 32; s; s >>= 1) {
        if (t < s) smr[t] += smr[t + s];
        __syncthreads();
    }
    if (t == 0) out[0] = smr[0] * (1.f / BATCH);
}

// ---------------------------------------------------------------------------
// logits output
// ---------------------------------------------------------------------------
__global__ void __launch_bounds__(256) logits_kernel(float* __restrict__ out) {
    const size_t n = (size_t)BATCH * ROW;
    float* otext  = out + 1 + BATCH;
    float* ostruc = otext + n;
    for (size_t i = blockIdx.x * (size_t)blockDim.x + threadIdx.x; i < n;
         i += (size_t)gridDim.x * blockDim.x) {
        otext[i]  = g_ht[i] + g_tt[i];
        ostruc[i] = g_hs[i] + g_ts[i];
    }
}

// ---------------------------------------------------------------------------
// Launch
// ---------------------------------------------------------------------------
extern "C" void kernel_launch(void* const* d_in, const int* in_sizes, int n_in,
                              void* d_out, int out_size) {
    const float* head_text  = (const float*)d_in[0];
    const float* tail_text  = (const float*)d_in[1];
    const float* head_struc = (const float*)d_in[2];
    const float* tail_struc = (const float*)d_in[3];
    const float* conf       = (const float*)d_in[4];
    const float* Wt1 = (const float*)d_in[5];
    const float* bt1 = (const float*)d_in[6];
    const float* Wt2 = (const float*)d_in[7];
    const float* bt2 = (const float*)d_in[8];
    const float* Ws1 = (const float*)d_in[9];
    const float* bs1 = (const float*)d_in[10];
    const float* Ws2 = (const float*)d_in[11];
    const float* bs2 = (const float*)d_in[12];
    const int*   perms = (const int*)d_in[13];
    float* out = (float*)d_out;

    // Pure queries — graph-capture safe.
    float *ht, *tt, *hs, *ts;
    cudaGetSymbolAddress((void**)&ht, g_ht);
    cudaGetSymbolAddress((void**)&tt, g_tt);
    cudaGetSymbolAddress((void**)&hs, g_hs);
    cudaGetSymbolAddress((void**)&ts, g_ts);
    __nv_bfloat16 *Ah, *Al, *Hh, *Hl;
    cudaGetSymbolAddress((void**)&Ah, g_Ah);
    cudaGetSymbolAddress((void**)&Al, g_Al);
    cudaGetSymbolAddress((void**)&Hh, g_Hh);
    cudaGetSymbolAddress((void**)&Hl, g_Hl);
    __nv_bfloat16 *wt1h, *wt1l, *wt2h, *wt2l, *ws1h, *ws1l, *ws2h, *ws2l;
    cudaGetSymbolAddress((void**)&wt1h, g_Wt1h);
    cudaGetSymbolAddress((void**)&wt1l, g_Wt1l);
    cudaGetSymbolAddress((void**)&wt2h, g_Wt2h);
    cudaGetSymbolAddress((void**)&wt2l, g_Wt2l);
    cudaGetSymbolAddress((void**)&ws1h, g_Ws1h);
    cudaGetSymbolAddress((void**)&ws1l, g_Ws1l);
    cudaGetSymbolAddress((void**)&ws2h, g_Ws2h);
    cudaGetSymbolAddress((void**)&ws2l, g_Ws2l);

    cudaFuncSetAttribute(mm2_kernel<768, 768, true,  true >, cudaFuncAttributeMaxDynamicSharedMemorySize, SMEM_MM);
    cudaFuncSetAttribute(mm2_kernel<256, 768, false, false>, cudaFuncAttributeMaxDynamicSharedMemorySize, SMEM_MM);
    cudaFuncSetAttribute(mm2_kernel<256, 256, true,  true >, cudaFuncAttributeMaxDynamicSharedMemorySize, SMEM_MM);
    cudaFuncSetAttribute(mm2_kernel<256, 256, false, false>, cudaFuncAttributeMaxDynamicSharedMemorySize, SMEM_MM);

    const dim3 blk(256);
    const dim3 gT1(768 / 128, MROWS / 128);   // (6, 384)
    const dim3 gT2(256 / 128, MROWS / 128);   // (2, 384)
    const int nT4 = MROWS * 768 / 4;          // text convert quads
    const int nS4 = MROWS * 256 / 4;          // struc convert quads

    // ---- text: head ----
    convert_a_kernel<<<(nT4 + 255) / 256, blk>>>(head_text, Ah, Al, nT4);
    convert_w_kernel<<<(768 * 768 + 255) / 256, blk>>>(Wt1, wt1h, wt1l, 768, 768);
    mm2_kernel<768, 768, true,  true ><<<gT1, blk, SMEM_MM>>>(Ah, Al, wt1h, wt1l, bt1, nullptr, Hh, Hl);
    convert_w_kernel<<<(768 * 256 + 255) / 256, blk>>>(Wt2, wt2h, wt2l, 768, 256);
    mm2_kernel<256, 768, false, false><<<gT2, blk, SMEM_MM>>>(Hh, Hl, wt2h, wt2l, bt2, ht, nullptr, nullptr);
    // ---- text: tail ----
    convert_a_kernel<<<(nT4 + 255) / 256, blk>>>(tail_text, Ah, Al, nT4);
    mm2_kernel<768, 768, true,  true ><<<gT1, blk, SMEM_MM>>>(Ah, Al, wt1h, wt1l, bt1, nullptr, Hh, Hl);
    mm2_kernel<256, 768, false, false><<<gT2, blk, SMEM_MM>>>(Hh, Hl, wt2h, wt2l, bt2, tt, nullptr, nullptr);
    // ---- struc: head ----
    convert_w_kernel<<<(256 * 256 + 255) / 256, blk>>>(Ws1, ws1h, ws1l, 256, 256);
    convert_w_kernel<<<(256 * 256 + 255) / 256, blk>>>(Ws2, ws2h, ws2l, 256, 256);
    convert_a_kernel<<<(nS4 + 255) / 256, blk>>>(head_struc, Ah, Al, nS4);
    mm2_kernel<256, 256, true,  true ><<<gT2, blk, SMEM_MM>>>(Ah, Al, ws1h, ws1l, bs1, nullptr, Hh, Hl);
    mm2_kernel<256, 256, false, false><<<gT2, blk, SMEM_MM>>>(Hh, Hl, ws2h, ws2l, bs2, hs, nullptr, nullptr);
    // ---- struc: tail ----
    convert_a_kernel<<<(nS4 + 255) / 256, blk>>>(tail_struc, Ah, Al, nS4);
    mm2_kernel<256, 256, true,  true ><<<gT2, blk, SMEM_MM>>>(Ah, Al, ws1h, ws1l, bs1, nullptr, Hh, Hl);
    mm2_kernel<256, 256, false, false><<<gT2, blk, SMEM_MM>>>(Hh, Hl, ws2h, ws2l, bs2, ts, nullptr, nullptr);

    // per-slot stats for both pairs
    stats_kernel<<<MROWS / 8, blk>>>(0);
    stats_kernel<<<MROWS / 8, blk>>>(1);

    // branch negatives + pos sims
    branch_kernel<<<2 * BATCH / 8, blk>>>(perms);

    // outputs
    score_loss_kernel<<<64, blk>>>(conf, out);
    loss_final_kernel<<<1, 64>>>(out, 64);
    logits_kernel<<<4096, blk>>>(out);
}